// round 5
// baseline (speedup 1.0000x reference)
#include <cuda_runtime.h>
#include <cstdint>

#define BS 32
#define NN 1024
#define FO 128
#define NWORDS 32
#define PACK_BLOCKS 512

#define RW 4                  // rows per warp
#define BW 4                  // batches per block/warp
#define WARPS 8
#define ROWS_PER_BLOCK 32     // RW * WARPS
#define KS 4                  // split-K factor
#define KW (NWORDS / KS)      // 8 adjacency words per slice
#define SLICE (KW * 32)       // 256 j's per slice

// Scratch (__device__ globals; no allocations allowed)
__device__ uint32_t g_adjw[NN * NWORDS];     // 128 KB packed adjacency
__device__ float    g_c1, g_c2;
__device__ float    g_meanx[BS];
__device__ float2   g_part[KS * BS * NN];    // {num, den} partials, 1 MB

// ---------------------------------------------------------------------------
// Setup: adjacency bit-pack (MLP=8/warp) + scalars c1,c2 + per-batch mean(x)
// ---------------------------------------------------------------------------
__global__ void __launch_bounds__(256) k_setup(const int* __restrict__ adj,
                                               const float* __restrict__ x,
                                               const float* __restrict__ W,
                                               const float* __restrict__ a) {
    int bid = blockIdx.x;
    int tid = threadIdx.x;

    if (bid < PACK_BLOCKS) {
        int warp = tid >> 5, lane = tid & 31;
        int wbase = (bid * WARPS + warp) * 8;
        int ebase = wbase * 32;
        int v[8];
#pragma unroll
        for (int r = 0; r < 8; r++)
            v[r] = adj[ebase + r * 32 + lane];
        uint32_t myw = 0;
#pragma unroll
        for (int r = 0; r < 8; r++) {
            unsigned m = __ballot_sync(0xffffffffu, v[r] > 0);
            if (lane == r) myw = m;
        }
        if (lane < 8) g_adjw[wbase + lane] = myw;
        return;
    }

    __shared__ float red[256];

    if (bid < PACK_BLOCKS + BS) {
        int b = bid - PACK_BLOCKS;
        float s = 0.f;
        for (int n = tid; n < NN; n += 256) s += x[b * NN + n];
        red[tid] = s; __syncthreads();
        for (int st = 128; st > 0; st >>= 1) {
            if (tid < st) red[tid] += red[tid + st];
            __syncthreads();
        }
        if (tid == 0) g_meanx[b] = red[0] * (1.0f / NN);
        return;
    }

    float p = (tid < FO) ? W[tid] * a[tid] : 0.f;
    red[tid] = p; __syncthreads();
    for (int st = 128; st > 0; st >>= 1) {
        if (tid < st) red[tid] += red[tid + st];
        __syncthreads();
    }
    if (tid == 0) g_c1 = red[0];
    __syncthreads();

    p = (tid < FO) ? W[tid] * a[FO + tid] : 0.f;
    red[tid] = p; __syncthreads();
    for (int st = 128; st > 0; st >>= 1) {
        if (tid < st) red[tid] += red[tid + st];
        __syncthreads();
    }
    if (tid == 0) g_c2 = red[0];
}

// ---------------------------------------------------------------------------
// Partial kernel: grid (rows/32, BS/4, KS). Warp = 4 rows x 4 batches over an
// 8-word j-slice. Transposed adjacency tile -> one LDS.128 per k-word.
// Exact keep-predicate: bit && (c2*x_j > -(c1*x_i)).
// ---------------------------------------------------------------------------
__global__ void __launch_bounds__(256) k_part(const float* __restrict__ x) {
    __shared__ float    s_x[BW][SLICE];       // 4 KB
    __shared__ uint32_t s_adjT[KW][32];       // 1 KB, [word][local row]

    int tid  = threadIdx.x;
    int lane = tid & 31;
    int warp = tid >> 5;
    int row0 = blockIdx.x * ROWS_PER_BLOCK;
    int b0   = blockIdx.y * BW;
    int kz   = blockIdx.z;

    // x slice: 4 batches x 256 j's (float4 loads)
    for (int t = tid; t < BW * (SLICE / 4); t += 256) {
        int b = t >> 6, jj = t & 63;
        reinterpret_cast<float4*>(s_x[b])[jj] =
            reinterpret_cast<const float4*>(x + (size_t)(b0 + b) * NN + kz * SLICE)[jj];
    }
    // adjacency transposed: s_adjT[kk][r]
    {
        int r = tid >> 3, kk = tid & 7;
        s_adjT[kk][r] = g_adjw[(row0 + r) * NWORDS + kz * KW + kk];
    }
    __syncthreads();

    const float c1 = g_c1, c2 = g_c2;
    const int ir = warp * RW;
    const uint32_t lanebit = 1u << lane;

    float nu[RW][BW];   // -c1*x_i (threshold)
    float den[RW][BW], num[RW][BW];
#pragma unroll
    for (int r = 0; r < RW; r++)
#pragma unroll
        for (int b = 0; b < BW; b++) {
            nu[r][b]  = -c1 * x[(size_t)(b0 + b) * NN + row0 + ir + r];
            den[r][b] = 0.f;
            num[r][b] = 0.f;
        }

#pragma unroll
    for (int kk = 0; kk < KW; kk++) {
        uint4 w = *reinterpret_cast<const uint4*>(&s_adjT[kk][ir]);  // LDS.128 bcast
#pragma unroll
        for (int b = 0; b < BW; b++) {
            float xv = s_x[b][kk * 32 + lane];
            float s2 = c2 * xv;
            float e2 = __expf(s2);
            if ((w.x & lanebit) && (s2 > nu[0][b])) { den[0][b] += e2; num[0][b] = fmaf(e2, xv, num[0][b]); }
            if ((w.y & lanebit) && (s2 > nu[1][b])) { den[1][b] += e2; num[1][b] = fmaf(e2, xv, num[1][b]); }
            if ((w.z & lanebit) && (s2 > nu[2][b])) { den[2][b] += e2; num[2][b] = fmaf(e2, xv, num[2][b]); }
            if ((w.w & lanebit) && (s2 > nu[3][b])) { den[3][b] += e2; num[3][b] = fmaf(e2, xv, num[3][b]); }
        }
    }

#pragma unroll
    for (int r = 0; r < RW; r++)
#pragma unroll
        for (int b = 0; b < BW; b++) {
            float d = den[r][b], nm = num[r][b];
#pragma unroll
            for (int o = 16; o > 0; o >>= 1) {
                d  += __shfl_xor_sync(0xffffffffu, d,  o);
                nm += __shfl_xor_sync(0xffffffffu, nm, o);
            }
            if (lane == 0)
                g_part[(size_t)kz * (BS * NN) + (size_t)(b0 + b) * NN + row0 + ir + r] =
                    make_float2(nm, d);
        }
}

// ---------------------------------------------------------------------------
// Epilogue: combine KS partials, y = num/den (or mean), out = elu(y*W).
// One thread per float4 of output. Store-bound (16 MB).
// ---------------------------------------------------------------------------
__device__ __forceinline__ float elu_fast(float v) {
    return v > 0.f ? v : (__expf(v) - 1.0f);
}

__global__ void __launch_bounds__(256) k_epi(const float* __restrict__ W,
                                             float* __restrict__ out) {
    int gid  = blockIdx.x * 256 + threadIdx.x;      // 0 .. BS*NN*32-1
    int row  = gid >> 5;                            // b*NN + i
    int lane = gid & 31;

    float num = 0.f, den = 0.f;
#pragma unroll
    for (int s = 0; s < KS; s++) {
        float2 p = g_part[(size_t)s * (BS * NN) + row];
        num += p.x; den += p.y;
    }
    float y = (den > 0.f) ? (num / den) : g_meanx[row >> 10];

    float4 wv = reinterpret_cast<const float4*>(W)[lane];
    float4 z;
    z.x = elu_fast(y * wv.x);
    z.y = elu_fast(y * wv.y);
    z.z = elu_fast(y * wv.z);
    z.w = elu_fast(y * wv.w);
    reinterpret_cast<float4*>(out)[gid] = z;
}

// ---------------------------------------------------------------------------
// Inputs per metadata order: input, adj, ext_input, side_input, W, a
// ---------------------------------------------------------------------------
extern "C" void kernel_launch(void* const* d_in, const int* in_sizes, int n_in,
                              void* d_out, int out_size) {
    const float* input = (const float*)d_in[0];
    const int*   adj   = (const int*)  d_in[1];
    const float* W     = (const float*)d_in[4];
    const float* a     = (const float*)d_in[5];
    float* out = (float*)d_out;

    k_setup<<<PACK_BLOCKS + BS + 1, 256>>>(adj, input, W, a);
    k_part<<<dim3(NN / ROWS_PER_BLOCK, BS / BW, KS), 256>>>(input);
    k_epi<<<(BS * NN * 32) / 256, 256>>>(W, out);
}

// round 7
// speedup vs baseline: 1.6747x; 1.6747x over previous
#include <cuda_runtime.h>
#include <cstdint>

#define BS 32
#define NN 1024
#define FO 128
#define NWORDS 32

#define RW 4                   // rows per warp
#define BW 2                   // batches per block/warp
#define WARPS 8
#define ROWS_PER_BLOCK 32      // RW * WARPS
#define PACK_BLOCKS 512        // pack: 512 blocks x 256 thr x 8 ints

// Scratch (__device__ globals; no allocations allowed)
__device__ uint32_t g_adjw[NN * NWORDS];   // 128 KB packed adjacency
__device__ float    g_c1, g_c2;
__device__ float    g_meanx[BS];

// ---------------------------------------------------------------------------
// Setup: pack adj via 2x LDG.128 per thread + shfl-OR byte pack; scalars;
// per-batch mean(x).
// ---------------------------------------------------------------------------
__global__ void __launch_bounds__(256) k_setup(const int* __restrict__ adj,
                                               const float* __restrict__ x,
                                               const float* __restrict__ W,
                                               const float* __restrict__ a) {
    int bid = blockIdx.x;
    int tid = threadIdx.x;

    if (bid < PACK_BLOCKS) {
        // thread t handles 8 consecutive ints -> one byte of a word
        int t = bid * 256 + tid;                 // global thread id
        const int4* a4 = reinterpret_cast<const int4*>(adj);
        int4 v0 = a4[2 * t];
        int4 v1 = a4[2 * t + 1];
        uint32_t m = 0;
        m |= (v0.x > 0) ? 1u   : 0u;
        m |= (v0.y > 0) ? 2u   : 0u;
        m |= (v0.z > 0) ? 4u   : 0u;
        m |= (v0.w > 0) ? 8u   : 0u;
        m |= (v1.x > 0) ? 16u  : 0u;
        m |= (v1.y > 0) ? 32u  : 0u;
        m |= (v1.z > 0) ? 64u  : 0u;
        m |= (v1.w > 0) ? 128u : 0u;
        int lane = tid & 31;
        uint32_t val = m << ((lane & 3) * 8);
        val |= __shfl_xor_sync(0xffffffffu, val, 1);
        val |= __shfl_xor_sync(0xffffffffu, val, 2);
        // warp covers 8 consecutive words; lane<8 gathers and stores
        uint32_t w = __shfl_sync(0xffffffffu, val, (lane & 7) * 4);
        int wbase = (t >> 5) * 8;                // first word of this warp
        if (lane < 8) g_adjw[wbase + lane] = w;
        return;
    }

    __shared__ float red[256];

    if (bid < PACK_BLOCKS + BS) {
        int b = bid - PACK_BLOCKS;
        float s = 0.f;
        for (int n = tid; n < NN; n += 256) s += x[b * NN + n];
        red[tid] = s; __syncthreads();
        for (int st = 128; st > 0; st >>= 1) {
            if (tid < st) red[tid] += red[tid + st];
            __syncthreads();
        }
        if (tid == 0) g_meanx[b] = red[0] * (1.0f / NN);
        return;
    }

    float p = (tid < FO) ? W[tid] * a[tid] : 0.f;
    red[tid] = p; __syncthreads();
    for (int st = 128; st > 0; st >>= 1) {
        if (tid < st) red[tid] += red[tid + st];
        __syncthreads();
    }
    if (tid == 0) g_c1 = red[0];
    __syncthreads();

    p = (tid < FO) ? W[tid] * a[FO + tid] : 0.f;
    red[tid] = p; __syncthreads();
    for (int st = 128; st > 0; st >>= 1) {
        if (tid < st) red[tid] += red[tid + st];
        __syncthreads();
    }
    if (tid == 0) g_c2 = red[0];
}

// ---------------------------------------------------------------------------
// Main: grid (32, 16), 256 threads. Warp = 4 rows x 2 batches.
// Transposed adj tile: one LDS.128 per k-word covers the warp's 4 rows.
// Keep-predicate identical to passing kernel: bit && (c2*x_j > -c1*x_i).
// ---------------------------------------------------------------------------
__device__ __forceinline__ float elu_fast(float v) {
    return v > 0.f ? v : (__expf(v) - 1.0f);
}

__global__ void __launch_bounds__(256, 4) k_main(const float* __restrict__ x,
                                                 const float* __restrict__ W,
                                                 float* __restrict__ out) {
    __shared__ float    s_x[BW][NN];          // 8 KB
    __shared__ uint32_t s_adjT[NWORDS][ROWS_PER_BLOCK];  // 4 KB, [word][row]
    __shared__ float    s_W[FO];              // 512 B

    int tid  = threadIdx.x;
    int lane = tid & 31;
    int warp = tid >> 5;
    int row0 = blockIdx.x * ROWS_PER_BLOCK;
    int b0   = blockIdx.y * BW;

    // x tile (float4)
    {
        const float4* src = reinterpret_cast<const float4*>(x + (size_t)b0 * NN);
        float4* dst = reinterpret_cast<float4*>(&s_x[0][0]);
        for (int t = tid; t < BW * NN / 4; t += 256) dst[t] = src[t];
    }
    // transposed adjacency tile
    for (int t = tid; t < ROWS_PER_BLOCK * NWORDS; t += 256) {
        int r = t >> 5, kk = t & 31;
        s_adjT[kk][r] = g_adjw[(row0 + r) * NWORDS + kk];
    }
    if (tid < FO) s_W[tid] = W[tid];
    __syncthreads();

    const float c1 = g_c1, c2 = g_c2;
    const int ir = warp * RW;
    const uint32_t lanebit = 1u << lane;

    float thr[RW][BW], den[RW][BW], num[RW][BW];
#pragma unroll
    for (int r = 0; r < RW; r++)
#pragma unroll
        for (int b = 0; b < BW; b++) {
            thr[r][b] = -c1 * s_x[b][row0 + ir + r];
            den[r][b] = 0.f;
            num[r][b] = 0.f;
        }

#pragma unroll 4
    for (int kk = 0; kk < NWORDS; kk++) {
        uint4 w = *reinterpret_cast<const uint4*>(&s_adjT[kk][ir]);  // LDS.128
        bool p0 = (w.x & lanebit) != 0;
        bool p1 = (w.y & lanebit) != 0;
        bool p2 = (w.z & lanebit) != 0;
        bool p3 = (w.w & lanebit) != 0;
#pragma unroll
        for (int b = 0; b < BW; b++) {
            float xv = s_x[b][kk * 32 + lane];
            float s2 = c2 * xv;
            float e2 = __expf(s2);
            if (p0 && (s2 > thr[0][b])) { den[0][b] += e2; num[0][b] = fmaf(e2, xv, num[0][b]); }
            if (p1 && (s2 > thr[1][b])) { den[1][b] += e2; num[1][b] = fmaf(e2, xv, num[1][b]); }
            if (p2 && (s2 > thr[2][b])) { den[2][b] += e2; num[2][b] = fmaf(e2, xv, num[2][b]); }
            if (p3 && (s2 > thr[3][b])) { den[3][b] += e2; num[3][b] = fmaf(e2, xv, num[3][b]); }
        }
    }

    float meanx[BW];
#pragma unroll
    for (int b = 0; b < BW; b++) meanx[b] = g_meanx[b0 + b];

    const float4 wv = reinterpret_cast<const float4*>(s_W)[lane];

#pragma unroll
    for (int r = 0; r < RW; r++) {
        int i = row0 + ir + r;
#pragma unroll
        for (int b = 0; b < BW; b++) {
            float d = den[r][b], nm = num[r][b];
#pragma unroll
            for (int o = 16; o > 0; o >>= 1) {
                d  += __shfl_xor_sync(0xffffffffu, d,  o);
                nm += __shfl_xor_sync(0xffffffffu, nm, o);
            }
            float y = (d > 0.f) ? (nm / d) : meanx[b];
            float4 z;
            z.x = elu_fast(y * wv.x);
            z.y = elu_fast(y * wv.y);
            z.z = elu_fast(y * wv.z);
            z.w = elu_fast(y * wv.w);
            reinterpret_cast<float4*>(out)[((size_t)(b0 + b) * NN + i) * (FO / 4) + lane] = z;
        }
    }
}

// ---------------------------------------------------------------------------
// Inputs per metadata order: input, adj, ext_input, side_input, W, a
// ---------------------------------------------------------------------------
extern "C" void kernel_launch(void* const* d_in, const int* in_sizes, int n_in,
                              void* d_out, int out_size) {
    const float* input = (const float*)d_in[0];
    const int*   adj   = (const int*)  d_in[1];
    const float* W     = (const float*)d_in[4];
    const float* a     = (const float*)d_in[5];
    float* out = (float*)d_out;

    k_setup<<<PACK_BLOCKS + BS + 1, 256>>>(adj, input, W, a);
    k_main<<<dim3(NN / ROWS_PER_BLOCK, BS / BW), 256>>>(input, W, out);
}